// round 2
// baseline (speedup 1.0000x reference)
#include <cuda_runtime.h>
#include <math.h>

// Problem constants
#define B_    2
#define N_    2048
#define E_    768
#define H_    12
#define D_    64
#define M_    (B_ * N_)       // 4096
#define QKV_N (3 * E_)        // 2304

// Scratch (device globals — allocation is forbidden)
__device__ __align__(16) float g_qkv[(size_t)M_ * QKV_N];  // [B*N, 2304]
__device__ __align__(16) float g_ctx[(size_t)M_ * E_];     // [B*N, 768]

// ---------------------------------------------------------------------------
// SGEMM: out[m, n] = sum_k X[m,k] * W[n,k] + bias[n]
// Block tile 128x128, K-tile 16, 256 threads, 8x8 per thread.
// ---------------------------------------------------------------------------
__global__ __launch_bounds__(256)
void sgemm_kernel(const float* __restrict__ X,
                  const float* __restrict__ W,
                  const float* __restrict__ bias,
                  float* __restrict__ out,
                  int K, int ldOut)
{
    __shared__ __align__(16) float As[16][132];
    __shared__ __align__(16) float Bs[16][132];

    const int bm = blockIdx.y * 128;
    const int bn = blockIdx.x * 128;
    const int tid = threadIdx.x;
    const int tx = tid & 15;          // n direction
    const int ty = tid >> 4;          // m direction

    float acc[8][8];
#pragma unroll
    for (int i = 0; i < 8; i++)
#pragma unroll
        for (int j = 0; j < 8; j++) acc[i][j] = 0.0f;

    const int lrow = tid >> 2;        // 0..63
    const int lc4  = tid & 3;         // 0..3

    for (int k0 = 0; k0 < K; k0 += 16) {
        // A tile (128 x 16) -> As[k][m]
#pragma unroll
        for (int r = 0; r < 128; r += 64) {
            int row = lrow + r;
            const float* src = X + (size_t)(bm + row) * K + k0 + lc4 * 4;
            float a0 = src[0], a1 = src[1], a2 = src[2], a3 = src[3];
            As[lc4 * 4 + 0][row] = a0;
            As[lc4 * 4 + 1][row] = a1;
            As[lc4 * 4 + 2][row] = a2;
            As[lc4 * 4 + 3][row] = a3;
        }
        // B tile: Bs[k][n] = W[(bn+n)*K + k0 + k]
#pragma unroll
        for (int r = 0; r < 128; r += 64) {
            int n = lrow + r;
            const float* src = W + (size_t)(bn + n) * K + k0 + lc4 * 4;
            float b0 = src[0], b1 = src[1], b2 = src[2], b3 = src[3];
            Bs[lc4 * 4 + 0][n] = b0;
            Bs[lc4 * 4 + 1][n] = b1;
            Bs[lc4 * 4 + 2][n] = b2;
            Bs[lc4 * 4 + 3][n] = b3;
        }
        __syncthreads();

#pragma unroll
        for (int k = 0; k < 16; k++) {
            float a[8], b[8];
#pragma unroll
            for (int i = 0; i < 8; i++) a[i] = As[k][ty * 8 + i];
#pragma unroll
            for (int j = 0; j < 8; j++) b[j] = Bs[k][tx * 8 + j];
#pragma unroll
            for (int i = 0; i < 8; i++)
#pragma unroll
                for (int j = 0; j < 8; j++)
                    acc[i][j] = fmaf(a[i], b[j], acc[i][j]);
        }
        __syncthreads();
    }

#pragma unroll
    for (int i = 0; i < 8; i++) {
        int m = bm + ty * 8 + i;
#pragma unroll
        for (int j = 0; j < 8; j++) {
            int n = bn + tx * 8 + j;
            out[(size_t)m * ldOut + n] = acc[i][j] + bias[n];
        }
    }
}

// ---------------------------------------------------------------------------
// Flash attention reading q/k/v directly from g_qkv [B*N, 2304].
// Row of head h for token (b, n):
//   q: g_qkv[(b*2048+n)*2304 + h*192 +   0 .. 63]
//   k: g_qkv[(b*2048+n)*2304 + h*192 +  64 .. 127]
//   v: g_qkv[(b*2048+n)*2304 + h*192 + 128 .. 191]
// One block = (b,h) x 128-query tile; one thread = 1 query row.
// ---------------------------------------------------------------------------
__global__ __launch_bounds__(128)
void attn_kernel()
{
    const int bh  = blockIdx.y;           // 0..23
    const int bb  = bh / H_;
    const int h   = bh - bb * H_;
    const int q0  = blockIdx.x * 128;
    const int tid = threadIdx.x;

    const float scale = rsqrtf((float)E_);
    const size_t rowbase = (size_t)bb * N_ * QKV_N + (size_t)h * 192;

    __shared__ __align__(16) float Ks[64 * 64];
    __shared__ __align__(16) float Vs[64 * 64];

    // Load this thread's query row (64 contiguous floats)
    float q[64];
    {
        const float* qr = g_qkv + rowbase + (size_t)(q0 + tid) * QKV_N;
#pragma unroll
        for (int t = 0; t < 64; t++) q[t] = qr[t];
    }

    float o[64];
#pragma unroll
    for (int i = 0; i < 64; i++) o[i] = 0.0f;
    float mx = -1e30f;
    float l  = 0.0f;

    for (int k0 = 0; k0 < N_; k0 += 64) {
        __syncthreads();
        // Load K/V 64x64 tiles. 1024 float4 each; 128 threads x 8.
        {
            const int c4 = (tid & 15) * 4;            // column (float offset)
            const int r0 = tid >> 4;                  // 0..7
#pragma unroll
            for (int i = 0; i < 8; i++) {
                int row = r0 + i * 8;                 // 0..63
                const float* krow = g_qkv + rowbase + (size_t)(k0 + row) * QKV_N + 64;
                const float* vrow = g_qkv + rowbase + (size_t)(k0 + row) * QKV_N + 128;
                Ks[row * 64 + c4 + 0] = krow[c4 + 0];
                Ks[row * 64 + c4 + 1] = krow[c4 + 1];
                Ks[row * 64 + c4 + 2] = krow[c4 + 2];
                Ks[row * 64 + c4 + 3] = krow[c4 + 3];
                Vs[row * 64 + c4 + 0] = vrow[c4 + 0];
                Vs[row * 64 + c4 + 1] = vrow[c4 + 1];
                Vs[row * 64 + c4 + 2] = vrow[c4 + 2];
                Vs[row * 64 + c4 + 3] = vrow[c4 + 3];
            }
        }
        __syncthreads();

        // 16-key register chunks
#pragma unroll
        for (int kc = 0; kc < 64; kc += 16) {
            float s[16];
#pragma unroll
            for (int jj = 0; jj < 16; jj++) {
                const float* kr = Ks + (kc + jj) * 64;
                float a = 0.0f;
#pragma unroll
                for (int t = 0; t < 64; t++) a = fmaf(q[t], kr[t], a);
                s[jj] = a * scale;
            }
            float mt = mx;
#pragma unroll
            for (int jj = 0; jj < 16; jj++) mt = fmaxf(mt, s[jj]);
            float alpha = __expf(mx - mt);
            l *= alpha;
#pragma unroll
            for (int i = 0; i < 64; i++) o[i] *= alpha;
#pragma unroll
            for (int jj = 0; jj < 16; jj++) {
                float p = __expf(s[jj] - mt);
                l += p;
                const float* vr = Vs + (kc + jj) * 64;
#pragma unroll
                for (int t = 0; t < 64; t++) o[t] = fmaf(p, vr[t], o[t]);
            }
            mx = mt;
        }
    }

    // ctx[b, q, h*64 + dd]
    const float inv = 1.0f / l;
    float* dst = g_ctx + ((size_t)bb * N_ + (q0 + tid)) * E_ + h * D_;
#pragma unroll
    for (int t = 0; t < 64; t++) dst[t] = o[t] * inv;
}

// ---------------------------------------------------------------------------
extern "C" void kernel_launch(void* const* d_in, const int* in_sizes, int n_in,
                              void* d_out, int out_size)
{
    const float* x     = (const float*)d_in[0];
    const float* w_qkv = (const float*)d_in[1];
    const float* b_qkv = (const float*)d_in[2];
    const float* w_o   = (const float*)d_in[3];
    const float* b_o   = (const float*)d_in[4];
    float* out = (float*)d_out;

    float* qkv_ptr;
    float* ctx_ptr;
    cudaGetSymbolAddress((void**)&qkv_ptr, g_qkv);
    cudaGetSymbolAddress((void**)&ctx_ptr, g_ctx);

    // 1) QKV projection: [4096,768] x [2304,768]^T -> g_qkv [4096, 2304]
    sgemm_kernel<<<dim3(QKV_N / 128, M_ / 128), 256>>>(x, w_qkv, b_qkv, qkv_ptr, E_, QKV_N);

    // 2) Attention: g_qkv -> g_ctx [4096, 768]
    attn_kernel<<<dim3(N_ / 128, B_ * H_), 128>>>();

    // 3) Output projection: [4096,768] x [768,768]^T -> d_out
    sgemm_kernel<<<dim3(E_ / 128, M_ / 128), 256>>>(ctx_ptr, w_o, b_o, out, E_, E_);
}